// round 12
// baseline (speedup 1.0000x reference)
#include <cuda_runtime.h>
#include <math.h>

// ---------------- problem constants ----------------
#define BB       2
#define SEQ      2048
#define DMODEL   1024
#define DCONV    4
#define HEADDIM  64
#define CHUNKL   256
#define DINNER   2048
#define NHEADS   32
#define CONVDIM  2304
#define DINPROJ  4384
#define DSTATE   128
#define DFF      4096
#define NC       8
#define NROWS    (BB*SEQ)   // 4096

// ---------------- scratch ----------------
__device__ float g_zx[(size_t)NROWS*DINPROJ];
__device__ float g_xbc[(size_t)NROWS*CONVDIM];
__device__ float g_xdt[(size_t)NROWS*DINNER];
__device__ float g_dt[(size_t)NROWS*NHEADS];
__device__ float g_draw[(size_t)NROWS*NHEADS];
__device__ float g_acum[(size_t)BB*NHEADS*SEQ];
__device__ float g_G[(size_t)BB*NC*CHUNKL*CHUNKL];
__device__ float g_states[(size_t)BB*NC*NHEADS*HEADDIM*DSTATE];
__device__ float g_prev  [(size_t)BB*NC*NHEADS*HEADDIM*DSTATE];
__device__ float g_y[(size_t)NROWS*DINNER];
__device__ float g_hidden[(size_t)NROWS*DMODEL];
__device__ float g_h[(size_t)NROWS*DMODEL];
__device__ float g_ff2[(size_t)NROWS*DMODEL];
// bf16 hi/lo packed operands (u32 = 2 bf16, k-pairs)
__device__ unsigned g_xhi[(size_t)NROWS*DMODEL/2],  g_xlo[(size_t)NROWS*DMODEL/2];
__device__ unsigned g_WinT_hi[(size_t)DINPROJ*DMODEL/2], g_WinT_lo[(size_t)DINPROJ*DMODEL/2];
__device__ unsigned g_WoutT_hi[(size_t)DMODEL*DINNER/2], g_WoutT_lo[(size_t)DMODEL*DINNER/2];
__device__ unsigned g_f1T_hi[(size_t)DFF*DMODEL/2],  g_f1T_lo[(size_t)DFF*DMODEL/2];
__device__ unsigned g_f2T_hi[(size_t)DMODEL*DFF/2],  g_f2T_lo[(size_t)DMODEL*DFF/2];
__device__ unsigned g_yhi[(size_t)NROWS*DINNER/2],   g_ylo[(size_t)NROWS*DINNER/2];
__device__ unsigned g_hhi[(size_t)NROWS*DMODEL/2],   g_hlo[(size_t)NROWS*DMODEL/2];
__device__ unsigned g_ffhi[(size_t)NROWS*DFF/2],     g_fflo[(size_t)NROWS*DFF/2];

// ---------------- helpers ----------------
__device__ __forceinline__ float softplusf(float x) {
    return (x > 20.f) ? x : log1pf(expf(x));
}
__device__ __forceinline__ float siluf(float x) {
    return x / (1.f + expf(-x));
}
__device__ __forceinline__ float tf32r(float x) {
    unsigned r;
    asm("cvt.rna.tf32.f32 %0, %1;" : "=r"(r) : "f"(x));
    return __uint_as_float(r);
}
__device__ __forceinline__ unsigned smem_u32(const void* p) {
    unsigned a;
    asm("{ .reg .u64 t; cvta.to.shared.u64 t, %1; cvt.u32.u64 %0, t; }" : "=r"(a) : "l"(p));
    return a;
}
__device__ __forceinline__ void mma_tf32(float* c, const unsigned* a, const unsigned* b) {
    asm volatile("mma.sync.aligned.m16n8k8.row.col.f32.tf32.tf32.f32 "
                 "{%0,%1,%2,%3}, {%4,%5,%6,%7}, {%8,%9}, {%0,%1,%2,%3};"
                 : "+f"(c[0]), "+f"(c[1]), "+f"(c[2]), "+f"(c[3])
                 : "r"(a[0]), "r"(a[1]), "r"(a[2]), "r"(a[3]),
                   "r"(b[0]), "r"(b[1]));
}
__device__ __forceinline__ void mma_bf16(float* c, const unsigned* a, const unsigned* b) {
    asm volatile("mma.sync.aligned.m16n8k16.row.col.f32.bf16.bf16.f32 "
                 "{%0,%1,%2,%3}, {%4,%5,%6,%7}, {%8,%9}, {%0,%1,%2,%3};"
                 : "+f"(c[0]), "+f"(c[1]), "+f"(c[2]), "+f"(c[3])
                 : "r"(a[0]), "r"(a[1]), "r"(a[2]), "r"(a[3]),
                   "r"(b[0]), "r"(b[1]));
}
// pack (f0 -> low bf16, f1 -> high bf16); lo = bf16 residual
__device__ __forceinline__ void split2(float f0, float f1, unsigned& hi, unsigned& lo) {
    unsigned h;
    asm("cvt.rn.bf16x2.f32 %0, %1, %2;" : "=r"(h) : "f"(f1), "f"(f0));
    float h0 = __uint_as_float(h << 16);
    float h1 = __uint_as_float(h & 0xffff0000u);
    unsigned l;
    asm("cvt.rn.bf16x2.f32 %0, %1, %2;" : "=r"(l) : "f"(f1 - h1), "f"(f0 - h0));
    hi = h; lo = l;
}

// ---------------- conversion kernels ----------------
// A-side: fp32 [M][K] row-major -> hi/lo u32 [M][K/2]
__global__ void convA_kernel(const float* __restrict__ src, unsigned* __restrict__ hi,
                             unsigned* __restrict__ lo, int n2)
{
    int i = blockIdx.x * blockDim.x + threadIdx.x;
    if (i >= n2) return;
    float2 v = ((const float2*)src)[i];
    unsigned h, l;
    split2(v.x, v.y, h, l);
    hi[i] = h; lo[i] = l;
}
// B-side: fp32 [K][N] -> transposed hi/lo u32 [N][K/2]
__global__ void convBT_kernel(const float* __restrict__ src, unsigned* __restrict__ hi,
                              unsigned* __restrict__ lo, int K, int N)
{
    __shared__ float ts[32][33];
    int n0 = blockIdx.x * 32, k0 = blockIdx.y * 32;
    int t = threadIdx.x;
    int r = t >> 3, c4 = (t & 7) * 4;
    float4 v = *(const float4*)(src + (size_t)(k0 + r) * N + n0 + c4);
    ts[r][c4 + 0] = v.x; ts[r][c4 + 1] = v.y; ts[r][c4 + 2] = v.z; ts[r][c4 + 3] = v.w;
    __syncthreads();
#pragma unroll
    for (int u = 0; u < 2; u++) {
        int idx = t * 2 + u;
        int n = idx >> 4, kp = idx & 15;
        unsigned h, l;
        split2(ts[2 * kp][n], ts[2 * kp + 1][n], h, l);
        size_t o = (size_t)(n0 + n) * (K / 2) + (k0 >> 1) + kp;
        hi[o] = h; lo[o] = l;
    }
}

// ---------------- bf16 hi/lo split GEMM: C = act(A@B + bias) ----------------
// operands pre-packed: A [M][K2] u32, B [N][K2] u32 (transposed). K2 = K/2.
// CTA 128x128, warp 32x64, 4-stage cp.async pipeline, K16 per stage.
#define GBS     4
#define RSTR    12                        // u32 per smem row (8 data + 4 pad)
#define AB_STF  (128*RSTR)                // 1536 u32 per array per stage
#define STG_U   (4*AB_STF)                // 6144 u32 per stage
#define GB_SMEM (GBS*STG_U*4)             // 98304 bytes

#define GB_ISSUE(stg, kt) do {                                                       \
    unsigned sb = smb + (unsigned)(stg) * (STG_U * 4);                               \
    int m_ = tid >> 1, hf_ = (tid & 1) * 4;                                          \
    unsigned ko = (unsigned)(kt) * 8 + hf_;                                          \
    const unsigned* a1 = Ahi + (size_t)(row0 + m_) * K2 + ko;                        \
    const unsigned* a2 = Alo + (size_t)(row0 + m_) * K2 + ko;                        \
    unsigned d_ = (unsigned)(m_ * RSTR + hf_) * 4;                                   \
    asm volatile("cp.async.cg.shared.global [%0], [%1], 16;" :: "r"(sb + d_), "l"(a1)); \
    asm volatile("cp.async.cg.shared.global [%0], [%1], 16;"                         \
                 :: "r"(sb + AB_STF * 4 + d_), "l"(a2));                             \
    int gn_ = col0 + m_;                                                             \
    const unsigned* b1 = (gn_ < N) ? (Bhi + (size_t)gn_ * K2 + ko) : Bhi;            \
    const unsigned* b2 = (gn_ < N) ? (Blo + (size_t)gn_ * K2 + ko) : Blo;            \
    int by_ = (gn_ < N) ? 16 : 0;                                                    \
    asm volatile("cp.async.cg.shared.global [%0], [%1], 16, %2;"                     \
                 :: "r"(sb + 2 * AB_STF * 4 + d_), "l"(b1), "r"(by_));               \
    asm volatile("cp.async.cg.shared.global [%0], [%1], 16, %2;"                     \
                 :: "r"(sb + 3 * AB_STF * 4 + d_), "l"(b2), "r"(by_));               \
    asm volatile("cp.async.commit_group;" ::: "memory");                             \
} while (0)

__global__ __launch_bounds__(256)
void gemm_bf(const unsigned* __restrict__ Ahi, const unsigned* __restrict__ Alo,
             const unsigned* __restrict__ Bhi, const unsigned* __restrict__ Blo,
             const float* __restrict__ bias, float* __restrict__ C,
             unsigned* __restrict__ Chi, unsigned* __restrict__ Clo,
             int M, int N, int K2, int act)
{
    extern __shared__ unsigned smu[];
    unsigned smb = smem_u32(smu);
    int tid = threadIdx.x;
    int lane = tid & 31, wid = tid >> 5;
    int wm = (wid >> 1) * 32;
    int wn = (wid & 1) * 64;
    int g = lane >> 2, tig = lane & 3;
    int row0 = blockIdx.y * 128, col0 = blockIdx.x * 128;

    float acc[2][8][4];
#pragma unroll
    for (int i = 0; i < 2; i++)
#pragma unroll
        for (int j = 0; j < 8; j++)
#pragma unroll
            for (int v = 0; v < 4; v++) acc[i][j][v] = 0.f;

    int nt = K2 / 8;            // K16 stages
    GB_ISSUE(0, 0);
    GB_ISSUE(1, 1);
    GB_ISSUE(2, 2);

    for (int t = 0; t < nt; t++) {
        if (t + 3 <= nt)      asm volatile("cp.async.wait_group 2;" ::: "memory");
        else if (t + 2 == nt) asm volatile("cp.async.wait_group 1;" ::: "memory");
        else                  asm volatile("cp.async.wait_group 0;" ::: "memory");
        __syncthreads();
        if (t + 3 < nt) { GB_ISSUE((t + 3) & 3, t + 3); }

        const unsigned* Sb = smu + (t & 3) * STG_U;
        const unsigned* Ah = Sb;
        const unsigned* Al = Sb + AB_STF;
        const unsigned* Bh = Sb + 2 * AB_STF;
        const unsigned* Bl = Sb + 3 * AB_STF;

        unsigned ah[2][4], bh[8][2];
#pragma unroll
        for (int mt = 0; mt < 2; mt++) {
            int m = wm + mt * 16;
            ah[mt][0] = Ah[(m + g) * RSTR + tig];
            ah[mt][1] = Ah[(m + g + 8) * RSTR + tig];
            ah[mt][2] = Ah[(m + g) * RSTR + tig + 4];
            ah[mt][3] = Ah[(m + g + 8) * RSTR + tig + 4];
        }
#pragma unroll
        for (int nt2 = 0; nt2 < 8; nt2++) {
            int n = wn + nt2 * 8;
            bh[nt2][0] = Bh[(n + g) * RSTR + tig];
            bh[nt2][1] = Bh[(n + g) * RSTR + tig + 4];
        }
        // pass hh
#pragma unroll
        for (int mt = 0; mt < 2; mt++)
#pragma unroll
            for (int nt2 = 0; nt2 < 8; nt2++)
                mma_bf16(acc[mt][nt2], ah[mt], bh[nt2]);
        // pass lh (A-lo x B-hi)
        {
            unsigned al[2][4];
#pragma unroll
            for (int mt = 0; mt < 2; mt++) {
                int m = wm + mt * 16;
                al[mt][0] = Al[(m + g) * RSTR + tig];
                al[mt][1] = Al[(m + g + 8) * RSTR + tig];
                al[mt][2] = Al[(m + g) * RSTR + tig + 4];
                al[mt][3] = Al[(m + g + 8) * RSTR + tig + 4];
            }
#pragma unroll
            for (int mt = 0; mt < 2; mt++)
#pragma unroll
                for (int nt2 = 0; nt2 < 8; nt2++)
                    mma_bf16(acc[mt][nt2], al[mt], bh[nt2]);
        }
        // pass hl (A-hi x B-lo)
        {
            unsigned bl[8][2];
#pragma unroll
            for (int nt2 = 0; nt2 < 8; nt2++) {
                int n = wn + nt2 * 8;
                bl[nt2][0] = Bl[(n + g) * RSTR + tig];
                bl[nt2][1] = Bl[(n + g) * RSTR + tig + 4];
            }
#pragma unroll
            for (int mt = 0; mt < 2; mt++)
#pragma unroll
                for (int nt2 = 0; nt2 < 8; nt2++)
                    mma_bf16(acc[mt][nt2], ah[mt], bl[nt2]);
        }
    }

    // epilogue
#pragma unroll
    for (int mt = 0; mt < 2; mt++) {
        int r = row0 + wm + mt * 16 + g;
#pragma unroll
        for (int nt2 = 0; nt2 < 8; nt2++) {
            int col = col0 + wn + nt2 * 8 + 2 * tig;
            if (col < N) {
                float b0 = bias[col], b1 = bias[col + 1];
                float v0 = acc[mt][nt2][0] + b0;
                float v1 = acc[mt][nt2][1] + b1;
                float v2 = acc[mt][nt2][2] + b0;
                float v3 = acc[mt][nt2][3] + b1;
                if (act == 1) {
                    float tt;
                    tt = fminf(fmaxf(v0 + 3.f, 0.f), 6.f); v0 = v0 * tt * (1.f / 6.f);
                    tt = fminf(fmaxf(v1 + 3.f, 0.f), 6.f); v1 = v1 * tt * (1.f / 6.f);
                    tt = fminf(fmaxf(v2 + 3.f, 0.f), 6.f); v2 = v2 * tt * (1.f / 6.f);
                    tt = fminf(fmaxf(v3 + 3.f, 0.f), 6.f); v3 = v3 * tt * (1.f / 6.f);
                    unsigned h0, l0, h1, l1;
                    split2(v0, v1, h0, l0);
                    split2(v2, v3, h1, l1);
                    size_t o0 = (size_t)r * (N / 2) + (col >> 1);
                    size_t o1 = (size_t)(r + 8) * (N / 2) + (col >> 1);
                    Chi[o0] = h0; Clo[o0] = l0;
                    Chi[o1] = h1; Clo[o1] = l1;
                } else {
                    C[(size_t)r * N + col] = v0;
                    C[(size_t)r * N + col + 1] = v1;
                    C[(size_t)(r + 8) * N + col] = v2;
                    C[(size_t)(r + 8) * N + col + 1] = v3;
                }
            }
        }
    }
}

// ---------------- exact fp32 dt_raw ----------------
__global__ void dtraw_kernel(const float* __restrict__ x, const float* __restrict__ W_in,
                             const float* __restrict__ b_in)
{
    int row0 = blockIdx.x * 8;
    int tid = threadIdx.x;
    int r = tid >> 5, h = tid & 31;
    __shared__ float xs[8][DMODEL];
    for (int i = tid; i < 8 * DMODEL; i += 256)
        xs[i >> 10][i & 1023] = x[(size_t)(row0 + (i >> 10)) * DMODEL + (i & 1023)];
    __syncthreads();
    const float* wc = W_in + (DINPROJ - NHEADS) + h;
    float a0 = 0.f, a1 = 0.f, a2 = 0.f, a3 = 0.f;
#pragma unroll 2
    for (int k = 0; k < DMODEL; k += 4) {
        a0 = fmaf(xs[r][k + 0], wc[(size_t)(k + 0) * DINPROJ], a0);
        a1 = fmaf(xs[r][k + 1], wc[(size_t)(k + 1) * DINPROJ], a1);
        a2 = fmaf(xs[r][k + 2], wc[(size_t)(k + 2) * DINPROJ], a2);
        a3 = fmaf(xs[r][k + 3], wc[(size_t)(k + 3) * DINPROJ], a3);
    }
    g_draw[(size_t)(row0 + r) * NHEADS + h] =
        b_in[DINPROJ - NHEADS + h] + ((a0 + a1) + (a2 + a3));
}

// ---------------- conv + silu + fused xdt ----------------
__global__ void conv_kernel(const float* __restrict__ conv_w, const float* __restrict__ conv_b)
{
    int idx = blockIdx.x * blockDim.x + threadIdx.x;
    if (idx >= (NROWS / 4) * CONVDIM) return;
    int ch = idx % CONVDIM;
    int rg = idx / CONVDIM;
    int row0 = rg * 4;
    int l0 = row0 % SEQ;
    float w0 = conv_w[ch * DCONV + 0], w1 = conv_w[ch * DCONV + 1];
    float w2 = conv_w[ch * DCONV + 2], w3 = conv_w[ch * DCONV + 3];
    float bv = conv_b[ch];
    float v[7];
#pragma unroll
    for (int j = 0; j < 7; j++) {
        int l = l0 + j - 3;
        v[j] = (l >= 0) ? g_zx[(size_t)(row0 + j - 3) * DINPROJ + DINNER + ch] : 0.f;
    }
#pragma unroll
    for (int i = 0; i < 4; i++) {
        float a = bv;
        a = fmaf(v[i], w0, a);
        a = fmaf(v[i + 1], w1, a);
        a = fmaf(v[i + 2], w2, a);
        a = fmaf(v[i + 3], w3, a);
        float o = siluf(a);
        size_t row = row0 + i;
        g_xbc[row * CONVDIM + ch] = o;
        if (ch < DINNER)
            g_xdt[row * DINNER + ch] = o * g_dt[row * NHEADS + (ch >> 6)];
    }
}

// ---------------- dt / dA + per-chunk inclusive cumsum ----------------
__global__ void dtscan_kernel(const float* __restrict__ tdiff,
                              const float* __restrict__ A_log,
                              const float* __restrict__ dt_bias,
                              const float* __restrict__ time_decay)
{
    int blk = blockIdx.x;
    int c = blk % NC;
    int h = (blk / NC) % NHEADS;
    int b = blk / (NC * NHEADS);
    int l = threadIdx.x;
    __shared__ float s[CHUNKL];
    int row = b * SEQ + c * CHUNKL + l;
    float draw = g_draw[(size_t)row * NHEADS + h];
    float dt = softplusf(draw + dt_bias[h]);
    float Ah = -expf(A_log[h]);
    float spd = softplusf(time_decay[h]);
    float dA = dt * Ah - spd * tdiff[row];
    g_dt[(size_t)row * NHEADS + h] = dt;
    s[l] = dA;
    __syncthreads();
    for (int off = 1; off < CHUNKL; off <<= 1) {
        float v = (l >= off) ? s[l - off] : 0.f;
        __syncthreads();
        s[l] += v;
        __syncthreads();
    }
    g_acum[((size_t)(b * NHEADS + h)) * SEQ + c * CHUNKL + l] = s[l];
}

// ---------------- G = C @ B^T per (b,chunk)  [tf32 mma] ----------------
__global__ __launch_bounds__(256)
void cbgemm_kernel()
{
    int bc = blockIdx.z;
    int l0 = blockIdx.y * 64, s0 = blockIdx.x * 64;
    __shared__ float As[16][72];
    __shared__ float Bs2[16][72];
    int tid = threadIdx.x;
    int lane = tid & 31, wid = tid >> 5;
    int wm = (wid & 3) * 16;
    int wn = (wid >> 2) * 32;
    int g = lane >> 2, tig = lane & 3;

    float acc[4][4];
#pragma unroll
    for (int j = 0; j < 4; j++)
#pragma unroll
        for (int v = 0; v < 4; v++) acc[j][v] = 0.f;

    const float* base = g_xbc + (size_t)bc * CHUNKL * CONVDIM;
    int r = tid >> 2, c4 = (tid & 3) << 2;
    for (int n0 = 0; n0 < DSTATE; n0 += 16) {
        float4 vc = *(const float4*)(base + (size_t)(l0 + r) * CONVDIM + DINNER + DSTATE + n0 + c4);
        As[c4 + 0][r] = tf32r(vc.x); As[c4 + 1][r] = tf32r(vc.y);
        As[c4 + 2][r] = tf32r(vc.z); As[c4 + 3][r] = tf32r(vc.w);
        float4 vb = *(const float4*)(base + (size_t)(s0 + r) * CONVDIM + DINNER + n0 + c4);
        Bs2[c4 + 0][r] = tf32r(vb.x); Bs2[c4 + 1][r] = tf32r(vb.y);
        Bs2[c4 + 2][r] = tf32r(vb.z); Bs2[c4 + 3][r] = tf32r(vb.w);
        __syncthreads();
#pragma unroll
        for (int ks = 0; ks < 2; ks++) {
            int kb = ks * 8;
            unsigned af[4], bf[4][2];
            af[0] = __float_as_uint(As[kb + tig][wm + g]);
            af[1] = __float_as_uint(As[kb + tig][wm + g + 8]);
            af[2] = __float_as_uint(As[kb + tig + 4][wm + g]);
            af[3] = __float_as_uint(As[kb + tig + 4][wm + g + 8]);
#pragma unroll
            for (int nt = 0; nt < 4; nt++) {
                int n = wn + nt * 8;
                bf[nt][0] = __float_as_uint(Bs2[kb + tig][n + g]);
                bf[nt][1] = __float_as_uint(Bs2[kb + tig + 4][n + g]);
            }
#pragma unroll
            for (int nt = 0; nt < 4; nt++)
                mma_tf32(acc[nt], af, bf[nt]);
        }
        __syncthreads();
    }
    float* Gp = g_G + (size_t)bc * CHUNKL * CHUNKL;
    int rr = l0 + wm + g;
#pragma unroll
    for (int nt = 0; nt < 4; nt++) {
        int col = s0 + wn + nt * 8 + 2 * tig;
        Gp[(size_t)rr * CHUNKL + col]     = acc[nt][0];
        Gp[(size_t)rr * CHUNKL + col + 1] = acc[nt][1];
        Gp[(size_t)(rr + 8) * CHUNKL + col]     = acc[nt][2];
        Gp[(size_t)(rr + 8) * CHUNKL + col + 1] = acc[nt][3];
    }
}

// ---------------- chunk states  [tf32 mma, __expf] ----------------
__global__ __launch_bounds__(256)
void states_kernel()
{
    int bch = blockIdx.x;
    int h = bch % NHEADS;
    int bc = bch / NHEADS;
    int b = bc / NC, c = bc % NC;
    int tid = threadIdx.x;
    int lane = tid & 31, wid = tid >> 5;
    int wm = (wid >> 1) * 16;
    int wn = (wid & 1) * 64;
    int g = lane >> 2, tig = lane & 3;

    __shared__ float w[CHUNKL];
    __shared__ float As[16][72];
    __shared__ float Bs[16][136];
    const float* ac = g_acum + ((size_t)(b * NHEADS + h)) * SEQ + c * CHUNKL;
    w[tid] = __expf(ac[CHUNKL - 1] - ac[tid]);
    __syncthreads();

    float acc[8][4];
#pragma unroll
    for (int j = 0; j < 8; j++)
#pragma unroll
        for (int v = 0; v < 4; v++) acc[j][v] = 0.f;

    for (int l0 = 0; l0 < CHUNKL; l0 += 16) {
        {
            int lr = tid >> 4, pc = (tid & 15) << 2;
            float4 v = *(const float4*)(g_xdt + ((size_t)(bc * CHUNKL + l0 + lr)) * DINNER + h * HEADDIM + pc);
            float ww = w[l0 + lr];
            As[lr][pc + 0] = tf32r(v.x * ww); As[lr][pc + 1] = tf32r(v.y * ww);
            As[lr][pc + 2] = tf32r(v.z * ww); As[lr][pc + 3] = tf32r(v.w * ww);
        }
#pragma unroll
        for (int u = 0; u < 2; u++) {
            int id = tid * 2 + u;
            int lr2 = id >> 5, nc4 = (id & 31) << 2;
            float4 vb = *(const float4*)(g_xbc + ((size_t)(bc * CHUNKL + l0 + lr2)) * CONVDIM + DINNER + nc4);
            Bs[lr2][nc4 + 0] = tf32r(vb.x); Bs[lr2][nc4 + 1] = tf32r(vb.y);
            Bs[lr2][nc4 + 2] = tf32r(vb.z); Bs[lr2][nc4 + 3] = tf32r(vb.w);
        }
        __syncthreads();
#pragma unroll
        for (int ks = 0; ks < 2; ks++) {
            int kb = ks * 8;
            unsigned af[4], bf[8][2];
            af[0] = __float_as_uint(As[kb + tig][wm + g]);
            af[1] = __float_as_uint(As[kb + tig][wm + g + 8]);
            af[2] = __float_as_uint(As[kb + tig + 4][wm + g]);
            af[3] = __float_as_uint(As[kb + tig + 4][wm + g + 8]);
#pragma unroll
            for (int nt = 0; nt < 8; nt++) {
                int n = wn + nt * 8;
                bf[nt][0] = __float_as_uint(Bs[kb + tig][n + g]);
                bf[nt][1] = __float_as_uint(Bs[kb + tig + 4][n + g]);
            }
#pragma unroll
            for (int nt = 0; nt < 8; nt++)
                mma_tf32(acc[nt], af, bf[nt]);
        }
        __syncthreads();
    }
    float* sp = g_states + (size_t)bch * HEADDIM * DSTATE;
    int r = wm + g;
#pragma unroll
    for (int nt = 0; nt < 8; nt++) {
        int col = wn + nt * 8 + 2 * tig;
        sp[(size_t)r * DSTATE + col]     = acc[nt][0];
        sp[(size_t)r * DSTATE + col + 1] = acc[nt][1];
        sp[(size_t)(r + 8) * DSTATE + col]     = acc[nt][2];
        sp[(size_t)(r + 8) * DSTATE + col + 1] = acc[nt][3];
    }
}

// ---------------- inter-chunk scan  [__expf] ----------------
__global__ void scan_kernel()
{
    int idx = blockIdx.x * blockDim.x + threadIdx.x;
    if (idx >= BB * NHEADS * HEADDIM * DSTATE) return;
    int n = idx & 127;
    int p = (idx >> 7) & 63;
    int h = (idx >> 13) & 31;
    int b = idx >> 18;
    float carry = 0.f;
    for (int c = 0; c < NC; c++) {
        size_t off = ((size_t)((b * NC + c) * NHEADS + h)) * (HEADDIM * DSTATE) + p * DSTATE + n;
        g_prev[off] = carry;
        float cd = __expf(g_acum[((size_t)(b * NHEADS + h)) * SEQ + c * CHUNKL + CHUNKL - 1]);
        carry = carry * cd + g_states[off];
    }
}

// ---------------- Y = (Y_diag + Y_off + D*xh) * silu(z)  [tf32 mma, __expf] -
__global__ __launch_bounds__(256)
void ydiag_kernel(const float* __restrict__ Dp)
{
    int bch = blockIdx.x;
    int h = bch % NHEADS;
    int bc = bch / NHEADS;
    int b = bc / NC;
    int tid = threadIdx.x;
    int lane = tid & 31, wid = tid >> 5;
    int g = lane >> 2, tig = lane & 3;
    int wm = wid * 32;

    __shared__ float Acs[CHUNKL];
    __shared__ float Gs[16][260];
    __shared__ float Xs[16][68];

    const float* ac = g_acum + ((size_t)(b * NHEADS + h)) * SEQ + (bc % NC) * CHUNKL;
    Acs[tid] = ac[tid];
    __syncthreads();
    float al = Acs[tid];
    float eal = __expf(al);

    float acc[2][8][4];
#pragma unroll
    for (int i = 0; i < 2; i++)
#pragma unroll
        for (int j = 0; j < 8; j++)
#pragma unroll
            for (int v = 0; v < 4; v++) acc[i][j][v] = 0.f;

    const float* Gp = g_G + (size_t)bc * CHUNKL * CHUNKL;

    for (int s0 = 0; s0 < CHUNKL; s0 += 16) {
        float4 gv[4];
#pragma unroll
        for (int q = 0; q < 4; q++)
            gv[q] = *(const float4*)(Gp + (size_t)tid * CHUNKL + s0 + q * 4);
        const float* gf = (const float*)gv;
#pragma unroll
        for (int i = 0; i < 16; i++) {
            int s = s0 + i;
            float v = 0.f;
            if (tid >= s) v = gf[i] * __expf(al - Acs[s]);
            Gs[i][tid] = tf32r(v);
        }
        {
            int lr = tid >> 4, pc = (tid & 15) << 2;
            float4 v4 = *(const float4*)(g_xdt + ((size_t)(bc * CHUNKL + s0 + lr)) * DINNER + h * HEADDIM + pc);
            Xs[lr][pc + 0] = tf32r(v4.x); Xs[lr][pc + 1] = tf32r(v4.y);
            Xs[lr][pc + 2] = tf32r(v4.z); Xs[lr][pc + 3] = tf32r(v4.w);
        }
        __syncthreads();
#pragma unroll
        for (int ks = 0; ks < 2; ks++) {
            int kb = ks * 8;
            unsigned af[2][4], bf[8][2];
#pragma unroll
            for (int mt = 0; mt < 2; mt++) {
                int m = wm + mt * 16;
                af[mt][0] = __float_as_uint(Gs[kb + tig][m + g]);
                af[mt][1] = __float_as_uint(Gs[kb + tig][m + g + 8]);
                af[mt][2] = __float_as_uint(Gs[kb + tig + 4][m + g]);
                af[mt][3] = __float_as_uint(Gs[kb + tig + 4][m + g + 8]);
            }
#pragma unroll
            for (int nt = 0; nt < 8; nt++) {
                int n = nt * 8;
                bf[nt][0] = __float_as_uint(Xs[kb + tig][n + g]);
                bf[nt][1] = __float_as_uint(Xs[kb + tig + 4][n + g]);
            }
#pragma unroll
            for (int mt = 0; mt < 2; mt++)
#pragma unroll
                for (int nt = 0; nt < 8; nt++)
                    mma_tf32(acc[mt][nt], af[mt], bf[nt]);
        }
        __syncthreads();
    }

    const float* pv_base = g_prev + (size_t)bch * HEADDIM * DSTATE;
    for (int n0 = 0; n0 < DSTATE; n0 += 16) {
        float4 cv[4];
#pragma unroll
        for (int q = 0; q < 4; q++)
            cv[q] = *(const float4*)(g_xbc + ((size_t)(bc * CHUNKL + tid)) * CONVDIM + DINNER + DSTATE + n0 + q * 4);
        const float* cf = (const float*)cv;
#pragma unroll
        for (int i = 0; i < 16; i++)
            Gs[i][tid] = tf32r(cf[i] * eal);
        {
            int p = tid >> 2, k4 = (tid & 3) << 2;
            float4 pvv = *(const float4*)(pv_base + (size_t)p * DSTATE + n0 + k4);
            Xs[k4 + 0][p] = tf32r(pvv.x); Xs[k4 + 1][p] = tf32r(pvv.y);
            Xs[k4 + 2][p] = tf32r(pvv.z); Xs[k4 + 3][p] = tf32r(pvv.w);
        }
        __syncthreads();
#pragma unroll
        for (int ks = 0; ks < 2; ks++) {
            int kb = ks * 8;
            unsigned af[2][4], bf[8][2];
#pragma unroll
            for (int mt = 0; mt < 2; mt++) {
                int m = wm + mt * 16;
                af[mt][0] = __float_as_uint(Gs[kb + tig][m + g]);
                af[mt][1] = __float_as_uint(Gs[kb + tig][m + g + 8]);
                af[mt][2] = __float_as_uint(Gs[kb + tig + 4][m + g]);
                af[mt][3] = __float_as_uint(Gs[kb + tig + 4][m + g + 8]);
            }
#pragma unroll
            for (int nt = 0; nt < 8; nt++) {
                int n = nt * 8;
                bf[nt][0] = __float_as_uint(Xs[kb + tig][n + g]);
                bf[nt][1] = __float_as_uint(Xs[kb + tig + 4][n + g]);
            }
#pragma unroll
            for (int mt = 0; mt < 2; mt++)
#pragma unroll
                for (int nt = 0; nt < 8; nt++)
                    mma_tf32(acc[mt][nt], af[mt], bf[nt]);
        }
        __syncthreads();
    }

    float Dh = Dp[h];
#pragma unroll
    for (int mt = 0; mt < 2; mt++) {
        int r0 = wm + mt * 16 + g;
#pragma unroll
        for (int nt = 0; nt < 8; nt++) {
            int pcol = nt * 8 + 2 * tig;
            int d = h * HEADDIM + pcol;
#pragma unroll
            for (int half = 0; half < 2; half++) {
                int l = r0 + half * 8;
                size_t row = (size_t)bc * CHUNKL + l;
                float xh0 = g_xbc[row * CONVDIM + d];
                float xh1 = g_xbc[row * CONVDIM + d + 1];
                float z0 = g_zx[row * DINPROJ + d];
                float z1 = g_zx[row * DINPROJ + d + 1];
                float v0 = acc[mt][nt][half * 2 + 0] + Dh * xh0;
                float v1 = acc[mt][nt][half * 2 + 1] + Dh * xh1;
                v0 *= siluf(z0);
                v1 *= siluf(z1);
                g_y[row * DINNER + d] = v0;
                g_y[row * DINNER + d + 1] = v1;
            }
        }
    }
}

// ---------------- gated RMS norm -> bf16 hi/lo pairs ----------------
__global__ void rms_kernel(const float* __restrict__ rms_w)
{
    int row = blockIdx.x;
    int tid = threadIdx.x;
    const float* y = g_y + (size_t)row * DINNER;
    float ss = 0.f;
    for (int i = tid; i < DINNER; i += 256) { float v = y[i]; ss = fmaf(v, v, ss); }
    __shared__ float red[256];
    red[tid] = ss; __syncthreads();
    for (int o = 128; o > 0; o >>= 1) { if (tid < o) red[tid] += red[tid + o]; __syncthreads(); }
    float scale = rsqrtf(red[0] * (1.f / DINNER) + 1e-12f);
    for (int i = tid * 2; i < DINNER; i += 512) {
        float v0 = y[i] * scale * rms_w[i];
        float v1 = y[i + 1] * scale * rms_w[i + 1];
        unsigned h, l;
        split2(v0, v1, h, l);
        size_t o = (size_t)row * (DINNER / 2) + (i >> 1);
        g_yhi[o] = h; g_ylo[o] = l;
    }
}

// ---------------- residual add + LayerNorm (+ optional bf16 pair output) ----
__global__ void addln_kernel(const float* __restrict__ in1, const float* __restrict__ res,
                             const float* __restrict__ g, const float* __restrict__ bta,
                             float* __restrict__ out,
                             unsigned* __restrict__ ohi, unsigned* __restrict__ olo)
{
    int row = blockIdx.x;
    int tid = threadIdx.x;
    __shared__ float buf[DMODEL];
    __shared__ float red[256];
    float s = 0.f;
    for (int i = tid; i < DMODEL; i += 256) {
        float v = in1[(size_t)row * DMODEL + i] + res[(size_t)row * DMODEL + i];
        buf[i] = v; s += v;
    }
    red[tid] = s; __syncthreads();
    for (int o = 128; o > 0; o >>= 1) { if (tid < o) red[tid] += red[tid + o]; __syncthreads(); }
    float mu = red[0] * (1.f / DMODEL);
    __syncthreads();
    float vs = 0.f;
    for (int i = tid; i < DMODEL; i += 256) { float d = buf[i] - mu; vs = fmaf(d, d, vs); }
    red[tid] = vs; __syncthreads();
    for (int o = 128; o > 0; o >>= 1) { if (tid < o) red[tid] += red[tid + o]; __syncthreads(); }
    float inv = rsqrtf(red[0] * (1.f / DMODEL) + 1e-12f);
    for (int i = tid * 2; i < DMODEL; i += 512) {
        float v0 = (buf[i] - mu) * inv * g[i] + bta[i];
        float v1 = (buf[i + 1] - mu) * inv * g[i + 1] + bta[i + 1];
        out[(size_t)row * DMODEL + i] = v0;
        out[(size_t)row * DMODEL + i + 1] = v1;
        if (ohi) {
            unsigned hh, ll;
            split2(v0, v1, hh, ll);
            size_t o = (size_t)row * (DMODEL / 2) + (i >> 1);
            ohi[o] = hh; olo[o] = ll;
        }
    }
}

// ---------------- launch ----------------
extern "C" void kernel_launch(void* const* d_in, const int* in_sizes, int n_in,
                              void* d_out, int out_size)
{
    const float* x          = (const float*)d_in[0];
    const float* time_diff  = (const float*)d_in[1];
    const float* W_in       = (const float*)d_in[2];
    const float* b_in       = (const float*)d_in[3];
    const float* conv_w     = (const float*)d_in[4];
    const float* conv_b     = (const float*)d_in[5];
    const float* A_log      = (const float*)d_in[6];
    const float* dt_bias    = (const float*)d_in[7];
    const float* Dp         = (const float*)d_in[8];
    const float* time_decay = (const float*)d_in[9];
    const float* rms_w      = (const float*)d_in[10];
    const float* W_out      = (const float*)d_in[11];
    const float* b_out      = (const float*)d_in[12];
    const float* ln_g       = (const float*)d_in[13];
    const float* ln_b       = (const float*)d_in[14];
    const float* fc1_w      = (const float*)d_in[15];
    const float* fc1_b      = (const float*)d_in[16];
    const float* fc2_w      = (const float*)d_in[17];
    const float* fc2_b      = (const float*)d_in[18];
    const float* ln2_g      = (const float*)d_in[19];
    const float* ln2_b      = (const float*)d_in[20];
    float* out = (float*)d_out;

    float *p_zx, *p_hidden, *p_h, *p_ff2;
    cudaGetSymbolAddress((void**)&p_zx, g_zx);
    cudaGetSymbolAddress((void**)&p_hidden, g_hidden);
    cudaGetSymbolAddress((void**)&p_h, g_h);
    cudaGetSymbolAddress((void**)&p_ff2, g_ff2);
    unsigned *p_xhi, *p_xlo, *p_WinT_hi, *p_WinT_lo, *p_WoutT_hi, *p_WoutT_lo;
    unsigned *p_f1T_hi, *p_f1T_lo, *p_f2T_hi, *p_f2T_lo;
    unsigned *p_yhi, *p_ylo, *p_hhi, *p_hlo, *p_ffhi, *p_fflo;
    cudaGetSymbolAddress((void**)&p_xhi, g_xhi);   cudaGetSymbolAddress((void**)&p_xlo, g_xlo);
    cudaGetSymbolAddress((void**)&p_WinT_hi, g_WinT_hi); cudaGetSymbolAddress((void**)&p_WinT_lo, g_WinT_lo);
    cudaGetSymbolAddress((void**)&p_WoutT_hi, g_WoutT_hi); cudaGetSymbolAddress((void**)&p_WoutT_lo, g_WoutT_lo);
    cudaGetSymbolAddress((void**)&p_f1T_hi, g_f1T_hi); cudaGetSymbolAddress((void**)&p_f1T_lo, g_f1T_lo);
    cudaGetSymbolAddress((void**)&p_f2T_hi, g_f2T_hi); cudaGetSymbolAddress((void**)&p_f2T_lo, g_f2T_lo);
    cudaGetSymbolAddress((void**)&p_yhi, g_yhi);   cudaGetSymbolAddress((void**)&p_ylo, g_ylo);
    cudaGetSymbolAddress((void**)&p_hhi, g_hhi);   cudaGetSymbolAddress((void**)&p_hlo, g_hlo);
    cudaGetSymbolAddress((void**)&p_ffhi, g_ffhi); cudaGetSymbolAddress((void**)&p_fflo, g_fflo);

    cudaFuncSetAttribute(gemm_bf, cudaFuncAttributeMaxDynamicSharedMemorySize, GB_SMEM);

    // 1. convert x -> bf16 hi/lo pairs
    convA_kernel<<<(NROWS * DMODEL / 2 + 255) / 256, 256>>>(x, p_xhi, p_xlo, NROWS * DMODEL / 2);
    // 2. convert+transpose W_in
    convBT_kernel<<<dim3(DINPROJ / 32, DMODEL / 32), 256>>>(W_in, p_WinT_hi, p_WinT_lo, DMODEL, DINPROJ);
    // 3. exact fp32 dt_raw
    dtraw_kernel<<<NROWS / 8, 256>>>(x, W_in, b_in);
    // 4. in_proj  [bf16 split]  (profiled launch)
    gemm_bf<<<dim3((DINPROJ + 127) / 128, NROWS / 128), 256, GB_SMEM>>>(
        p_xhi, p_xlo, p_WinT_hi, p_WinT_lo, b_in, p_zx, (unsigned*)0, (unsigned*)0,
        NROWS, DINPROJ, DMODEL / 2, 0);
    // 5. dt / dA / chunk cumsum
    dtscan_kernel<<<BB * NHEADS * NC, CHUNKL>>>(time_diff, A_log, dt_bias, time_decay);
    // 6. conv + silu + fused xdt
    conv_kernel<<<((NROWS / 4) * CONVDIM + 255) / 256, 256>>>(conv_w, conv_b);
    // 7. G = C @ B^T
    cbgemm_kernel<<<dim3(4, 4, BB * NC), 256>>>();
    // 8. chunk states
    states_kernel<<<BB * NC * NHEADS, 256>>>();
    // 9. inter-chunk scan
    scan_kernel<<<(BB * NHEADS * HEADDIM * DSTATE + 255) / 256, 256>>>();
    // 10. Y
    ydiag_kernel<<<BB * NC * NHEADS, 256>>>(Dp);
    // 11. gated RMS norm -> y hi/lo
    rms_kernel<<<NROWS, 256>>>(rms_w);
    // 12. convert+transpose W_out
    convBT_kernel<<<dim3(DMODEL / 32, DINNER / 32), 256>>>(W_out, p_WoutT_hi, p_WoutT_lo, DINNER, DMODEL);
    // 13. out_proj [bf16 split]
    gemm_bf<<<dim3(DMODEL / 128, NROWS / 128), 256, GB_SMEM>>>(
        p_yhi, p_ylo, p_WoutT_hi, p_WoutT_lo, b_out, p_hidden, (unsigned*)0, (unsigned*)0,
        NROWS, DMODEL, DINNER / 2, 0);
    // 14. h = LN(hidden + x)  (+ h hi/lo)
    addln_kernel<<<NROWS, 256>>>(p_hidden, x, ln_g, ln_b, p_h, p_hhi, p_hlo);
    // 15. convert+transpose fc1_w
    convBT_kernel<<<dim3(DFF / 32, DMODEL / 32), 256>>>(fc1_w, p_f1T_hi, p_f1T_lo, DMODEL, DFF);
    // 16. fc1 + hardswish [bf16 split] -> ff hi/lo directly
    gemm_bf<<<dim3(DFF / 128, NROWS / 128), 256, GB_SMEM>>>(
        p_hhi, p_hlo, p_f1T_hi, p_f1T_lo, fc1_b, (float*)0, p_ffhi, p_fflo,
        NROWS, DFF, DMODEL / 2, 1);
    // 17. convert+transpose fc2_w
    convBT_kernel<<<dim3(DMODEL / 32, DFF / 32), 256>>>(fc2_w, p_f2T_hi, p_f2T_lo, DFF, DMODEL);
    // 18. fc2 [bf16 split]
    gemm_bf<<<dim3(DMODEL / 128, NROWS / 128), 256, GB_SMEM>>>(
        p_ffhi, p_fflo, p_f2T_hi, p_f2T_lo, fc2_b, p_ff2, (unsigned*)0, (unsigned*)0,
        NROWS, DMODEL, DFF / 2, 0);
    // 19. out = LN(ff2 + h)
    addln_kernel<<<NROWS, 256>>>(p_ff2, p_h, ln2_g, ln2_b, out, (unsigned*)0, (unsigned*)0);
    // 20. time_diff passthrough
    cudaMemcpyAsync(out + (size_t)NROWS * DMODEL, time_diff,
                    (size_t)BB * SEQ * sizeof(float), cudaMemcpyDeviceToDevice);
}